// round 6
// baseline (speedup 1.0000x reference)
#include <cuda_runtime.h>
#include <math.h>

#define BB 4
#define TT 2048
#define CC 512
#define HH 8
#define DD 64
#define MM (BB*TT)          // 8192 rows
#define NCHUNK 16
#define EPSN 1e-4f

// ---------------- scratch (no allocation allowed) ----------------
__device__ float g_qkv[3u*MM*CC];          // raw Q,K,V projections  (~50 MB)
__device__ float g_attn[(size_t)MM*CC];    // attention output pre-Wo (~17 MB)
__device__ float g_partial[3*BB*NCHUNK*CC];
__device__ float g_inv[3*BB*CC];           // rsqrt(mean_t x^2 + eps) per (proj,b,c)

// ---------------- shared 64x64x32 SGEMM tile ----------------
__device__ __forceinline__ void gemm_tile_compute(const float* __restrict__ A,
                                                  const float* __restrict__ W,
                                                  float acc[4][4],
                                                  int row0, int col0)
{
    __shared__ float As[32][64];   // [k][m] transposed
    __shared__ float Ws[32][64];   // [k][n]
    const int tid = threadIdx.x;
    const int ty = tid >> 4, tx = tid & 15;

    for (int kk = 0; kk < CC; kk += 32) {
#pragma unroll
        for (int it = 0; it < 2; it++) {
            int l = tid + it * 256;          // 0..511 float4 of A tile
            int r = l >> 3, c4 = l & 7;
            float4 v = *(const float4*)(A + (size_t)(row0 + r) * CC + kk + c4 * 4);
            As[c4*4+0][r] = v.x; As[c4*4+1][r] = v.y;
            As[c4*4+2][r] = v.z; As[c4*4+3][r] = v.w;
        }
#pragma unroll
        for (int it = 0; it < 2; it++) {
            int l = tid + it * 256;          // 0..511 float4 of W tile
            int r = l >> 4, c4 = l & 15;
            *(float4*)&Ws[r][c4*4] =
                *(const float4*)(W + (size_t)(kk + r) * CC + col0 + c4 * 4);
        }
        __syncthreads();
#pragma unroll
        for (int k = 0; k < 32; k++) {
            float4 a = *(const float4*)&As[k][ty * 4];
            float4 b = *(const float4*)&Ws[k][tx * 4];
            acc[0][0] += a.x*b.x; acc[0][1] += a.x*b.y; acc[0][2] += a.x*b.z; acc[0][3] += a.x*b.w;
            acc[1][0] += a.y*b.x; acc[1][1] += a.y*b.y; acc[1][2] += a.y*b.z; acc[1][3] += a.y*b.w;
            acc[2][0] += a.z*b.x; acc[2][1] += a.z*b.y; acc[2][2] += a.z*b.z; acc[2][3] += a.z*b.w;
            acc[3][0] += a.w*b.x; acc[3][1] += a.w*b.y; acc[3][2] += a.w*b.z; acc[3][3] += a.w*b.w;
        }
        __syncthreads();
    }
}

// ---------------- kernel 1: Q,K,V projections ----------------
__global__ __launch_bounds__(256) void gemm_qkv_kernel(const float* __restrict__ X,
                                                       const float* __restrict__ Wq,
                                                       const float* __restrict__ Wk,
                                                       const float* __restrict__ Wv)
{
    const float* W = (blockIdx.z == 0) ? Wq : (blockIdx.z == 1 ? Wk : Wv);
    float* Out = g_qkv + (size_t)blockIdx.z * MM * CC;
    const int row0 = blockIdx.x * 64, col0 = blockIdx.y * 64;
    float acc[4][4] = {};
    gemm_tile_compute(X, W, acc, row0, col0);
    const int ty = threadIdx.x >> 4, tx = threadIdx.x & 15;
#pragma unroll
    for (int i = 0; i < 4; i++) {
        float4 v = make_float4(acc[i][0], acc[i][1], acc[i][2], acc[i][3]);
        *(float4*)(Out + (size_t)(row0 + ty*4 + i) * CC + col0 + tx * 4) = v;
    }
}

// ---------------- kernel 2: column sum-of-squares over T (partials) ----------------
__global__ __launch_bounds__(512) void sumsq_partial_kernel()
{
    const int ch = blockIdx.x, b = blockIdx.y, proj = blockIdx.z;
    const int c = threadIdx.x;
    const int trows = TT / NCHUNK;   // 128
    const float* p = g_qkv + ((size_t)proj * MM + (size_t)b * TT + (size_t)ch * trows) * CC;
    float s = 0.f;
#pragma unroll 4
    for (int t = 0; t < trows; t++) {
        float v = p[(size_t)t * CC + c];
        s += v * v;
    }
    g_partial[((proj * BB + b) * NCHUNK + ch) * CC + c] = s;
}

// ---------------- kernel 3: finalize inverse norms ----------------
__global__ __launch_bounds__(512) void inv_finalize_kernel()
{
    const int pb = blockIdx.x;       // proj*BB + b, 0..11
    const int c = threadIdx.x;
    float s = 0.f;
#pragma unroll
    for (int ch = 0; ch < NCHUNK; ch++)
        s += g_partial[(pb * NCHUNK + ch) * CC + c];
    g_inv[pb * CC + c] = rsqrtf(s * (1.0f / TT) + EPSN);
}

// ---------------- kernel 4: flash attention (fp32) ----------------
// Bq=64, Bkv=32, d=64; 256 threads; norm factors + softmax scale folded into loads.
__global__ __launch_bounds__(256) void attn_kernel()
{
    const int qt = blockIdx.x;            // 0..31
    const int bh = blockIdx.y;            // 0..31
    const int b = bh >> 3, h = bh & 7;

    const float* Qp = g_qkv + ((size_t)b * TT) * CC + h * DD;
    const float* Kp = g_qkv + (size_t)MM * CC + ((size_t)b * TT) * CC + h * DD;
    const float* Vp = g_qkv + 2ull * MM * CC + ((size_t)b * TT) * CC + h * DD;
    const float* invq = g_inv + (0 * BB + b) * CC + h * DD;
    const float* invk = g_inv + (1 * BB + b) * CC + h * DD;
    const float* invv = g_inv + (2 * BB + b) * CC + h * DD;

    __shared__ float Qs[64][68];   // [d][q]
    __shared__ float Ks[64][36];   // [d][kv]
    __shared__ float Vs[32][68];   // [kv][d]
    __shared__ float Ps[32][68];   // [kv][q]
    __shared__ float row_max[64], row_sum[64];

    const int tid = threadIdx.x;
    const int ty = tid >> 4, tx = tid & 15;
    const float scale = 0.125f;   // 1/sqrt(64)

    // load Q tile (transposed), scaled by invq * softmax scale
#pragma unroll
    for (int it = 0; it < 4; it++) {
        int l = tid + it * 256;           // 0..1023 float4
        int r = l >> 4, c4 = l & 15;
        float4 v = *(const float4*)(Qp + (size_t)(qt * 64 + r) * CC + c4 * 4);
        float4 s = *(const float4*)(invq + c4 * 4);
        Qs[c4*4+0][r] = v.x * s.x * scale;
        Qs[c4*4+1][r] = v.y * s.y * scale;
        Qs[c4*4+2][r] = v.z * s.z * scale;
        Qs[c4*4+3][r] = v.w * s.w * scale;
    }
    if (tid < 64) { row_max[tid] = -INFINITY; row_sum[tid] = 0.f; }

    float acc[4][4] = {};

    for (int kt = 0; kt < TT / 32; kt++) {
        __syncthreads();
        // load K (transposed) and V tiles, scaled by their inverse norms
#pragma unroll
        for (int it = 0; it < 2; it++) {
            int l = tid + it * 256;       // 0..511 float4
            int r = l >> 4, c4 = l & 15;
            float4 kv4 = *(const float4*)(Kp + (size_t)(kt * 32 + r) * CC + c4 * 4);
            float4 ks = *(const float4*)(invk + c4 * 4);
            Ks[c4*4+0][r] = kv4.x * ks.x;
            Ks[c4*4+1][r] = kv4.y * ks.y;
            Ks[c4*4+2][r] = kv4.z * ks.z;
            Ks[c4*4+3][r] = kv4.w * ks.w;
            float4 vv4 = *(const float4*)(Vp + (size_t)(kt * 32 + r) * CC + c4 * 4);
            float4 vs = *(const float4*)(invv + c4 * 4);
            float4 o;
            o.x = vv4.x * vs.x; o.y = vv4.y * vs.y;
            o.z = vv4.z * vs.z; o.w = vv4.w * vs.w;
            *(float4*)&Vs[r][c4 * 4] = o;
        }
        __syncthreads();

        // S = Q · K^T  (per-thread 4 q-rows x 2 kv-cols)
        float s[4][2] = {};
#pragma unroll
        for (int d = 0; d < 64; d++) {
            float4 a = *(const float4*)&Qs[d][ty * 4];
            float2 bq = *(const float2*)&Ks[d][tx * 2];
            s[0][0] += a.x * bq.x; s[0][1] += a.x * bq.y;
            s[1][0] += a.y * bq.x; s[1][1] += a.y * bq.y;
            s[2][0] += a.z * bq.x; s[2][1] += a.z * bq.y;
            s[3][0] += a.w * bq.x; s[3][1] += a.w * bq.y;
        }

        // online softmax: rows of a 16-lane group are convergent within a half-warp
        float mv[4], lv[4], fac[4];
#pragma unroll
        for (int i = 0; i < 4; i++) {
            float lm = fmaxf(s[i][0], s[i][1]);
#pragma unroll
            for (int off = 8; off; off >>= 1)
                lm = fmaxf(lm, __shfl_xor_sync(0xffffffffu, lm, off));
            float mold = row_max[ty * 4 + i];
            float mnew = fmaxf(mold, lm);
            fac[i] = __expf(mold - mnew);
            s[i][0] = __expf(s[i][0] - mnew);
            s[i][1] = __expf(s[i][1] - mnew);
            float ls = s[i][0] + s[i][1];
#pragma unroll
            for (int off = 8; off; off >>= 1)
                ls += __shfl_xor_sync(0xffffffffu, ls, off);
            mv[i] = mnew;
            lv[i] = row_sum[ty * 4 + i] * fac[i] + ls;
        }
        __syncwarp();
        if (tx == 0) {
#pragma unroll
            for (int i = 0; i < 4; i++) {
                row_max[ty * 4 + i] = mv[i];
                row_sum[ty * 4 + i] = lv[i];
            }
        }
        // rescale accumulators, stage P (transposed)
#pragma unroll
        for (int i = 0; i < 4; i++) {
            acc[i][0] *= fac[i]; acc[i][1] *= fac[i];
            acc[i][2] *= fac[i]; acc[i][3] *= fac[i];
            Ps[tx * 2 + 0][ty * 4 + i] = s[i][0];
            Ps[tx * 2 + 1][ty * 4 + i] = s[i][1];
        }
        __syncthreads();

        // O += P · V
#pragma unroll
        for (int kv = 0; kv < 32; kv++) {
            float4 p = *(const float4*)&Ps[kv][ty * 4];
            float4 v = *(const float4*)&Vs[kv][tx * 4];
            acc[0][0] += p.x*v.x; acc[0][1] += p.x*v.y; acc[0][2] += p.x*v.z; acc[0][3] += p.x*v.w;
            acc[1][0] += p.y*v.x; acc[1][1] += p.y*v.y; acc[1][2] += p.y*v.z; acc[1][3] += p.y*v.w;
            acc[2][0] += p.z*v.x; acc[2][1] += p.z*v.y; acc[2][2] += p.z*v.z; acc[2][3] += p.z*v.w;
            acc[3][0] += p.w*v.x; acc[3][1] += p.w*v.y; acc[3][2] += p.w*v.z; acc[3][3] += p.w*v.w;
        }
    }

    // normalize and write (row_sum last written before the Ps __syncthreads)
    float* Op = g_attn + ((size_t)b * TT + qt * 64) * CC + h * DD;
#pragma unroll
    for (int i = 0; i < 4; i++) {
        float il = 1.0f / row_sum[ty * 4 + i];
        float4 o = make_float4(acc[i][0] * il, acc[i][1] * il,
                               acc[i][2] * il, acc[i][3] * il);
        *(float4*)(Op + (size_t)(ty * 4 + i) * CC + tx * 4) = o;
    }
}

// ---------------- kernel 5: out-proj + bias + residual ----------------
__global__ __launch_bounds__(256) void gemm_out_kernel(const float* __restrict__ Wo,
                                                       const float* __restrict__ bo,
                                                       const float* __restrict__ residual,
                                                       float* __restrict__ Out)
{
    const int row0 = blockIdx.x * 64, col0 = blockIdx.y * 64;
    float acc[4][4] = {};
    gemm_tile_compute(g_attn, Wo, acc, row0, col0);
    const int ty = threadIdx.x >> 4, tx = threadIdx.x & 15;
    float4 bias = *(const float4*)(bo + col0 + tx * 4);
#pragma unroll
    for (int i = 0; i < 4; i++) {
        size_t off = (size_t)(row0 + ty*4 + i) * CC + col0 + tx * 4;
        float4 r = *(const float4*)(residual + off);
        float4 v = make_float4(acc[i][0] + bias.x + r.x,
                               acc[i][1] + bias.y + r.y,
                               acc[i][2] + bias.z + r.z,
                               acc[i][3] + bias.w + r.w);
        *(float4*)(Out + off) = v;
    }
}

// ---------------- launch ----------------
extern "C" void kernel_launch(void* const* d_in, const int* in_sizes, int n_in,
                              void* d_out, int out_size)
{
    (void)in_sizes; (void)n_in; (void)out_size;
    const float* X  = (const float*)d_in[0];
    const float* Wq = (const float*)d_in[1];
    const float* Wk = (const float*)d_in[2];
    const float* Wv = (const float*)d_in[3];
    const float* Wo = (const float*)d_in[4];
    const float* bo = (const float*)d_in[5];
    float* out = (float*)d_out;

    gemm_qkv_kernel<<<dim3(MM / 64, CC / 64, 3), 256>>>(X, Wq, Wk, Wv);
    sumsq_partial_kernel<<<dim3(NCHUNK, BB, 3), 512>>>();
    inv_finalize_kernel<<<dim3(3 * BB), 512>>>();
    attn_kernel<<<dim3(TT / 64, BB * HH), 256>>>();
    gemm_out_kernel<<<dim3(MM / 64, CC / 64), 256>>>(Wo, bo, X, out);
}

// round 9
// speedup vs baseline: 1.0009x; 1.0009x over previous
#include <cuda_runtime.h>
#include <math.h>

#define BB 4
#define TT 2048
#define CC 512
#define HH 8
#define DD 64
#define MM (BB*TT)          // 8192 rows
#define NCHUNK 16
#define EPSN 1e-4f

// ---------------- scratch (no allocation allowed) ----------------
__device__ float g_qkv[3u*MM*CC];          // raw Q,K,V projections  (~50 MB)
__device__ float g_attn[(size_t)MM*CC];    // attention output pre-Wo (~17 MB)
__device__ float g_partial[3*BB*NCHUNK*CC];
__device__ float g_inv[3*BB*CC];           // rsqrt(mean_t x^2 + eps) per (proj,b,c)

// ---------------- shared 64x64x32 SGEMM tile ----------------
__device__ __forceinline__ void gemm_tile_compute(const float* __restrict__ A,
                                                  const float* __restrict__ W,
                                                  float acc[4][4],
                                                  int row0, int col0)
{
    __shared__ float As[32][64];   // [k][m] transposed
    __shared__ float Ws[32][64];   // [k][n]
    const int tid = threadIdx.x;
    const int ty = tid >> 4, tx = tid & 15;

    for (int kk = 0; kk < CC; kk += 32) {
#pragma unroll
        for (int it = 0; it < 2; it++) {
            int l = tid + it * 256;          // 0..511 float4 of A tile
            int r = l >> 3, c4 = l & 7;
            float4 v = *(const float4*)(A + (size_t)(row0 + r) * CC + kk + c4 * 4);
            As[c4*4+0][r] = v.x; As[c4*4+1][r] = v.y;
            As[c4*4+2][r] = v.z; As[c4*4+3][r] = v.w;
        }
#pragma unroll
        for (int it = 0; it < 2; it++) {
            int l = tid + it * 256;          // 0..511 float4 of W tile
            int r = l >> 4, c4 = l & 15;
            *(float4*)&Ws[r][c4*4] =
                *(const float4*)(W + (size_t)(kk + r) * CC + col0 + c4 * 4);
        }
        __syncthreads();
#pragma unroll
        for (int k = 0; k < 32; k++) {
            float4 a = *(const float4*)&As[k][ty * 4];
            float4 b = *(const float4*)&Ws[k][tx * 4];
            acc[0][0] += a.x*b.x; acc[0][1] += a.x*b.y; acc[0][2] += a.x*b.z; acc[0][3] += a.x*b.w;
            acc[1][0] += a.y*b.x; acc[1][1] += a.y*b.y; acc[1][2] += a.y*b.z; acc[1][3] += a.y*b.w;
            acc[2][0] += a.z*b.x; acc[2][1] += a.z*b.y; acc[2][2] += a.z*b.z; acc[2][3] += a.z*b.w;
            acc[3][0] += a.w*b.x; acc[3][1] += a.w*b.y; acc[3][2] += a.w*b.z; acc[3][3] += a.w*b.w;
        }
        __syncthreads();
    }
}

// ---------------- kernel 1: Q,K,V projections ----------------
__global__ __launch_bounds__(256) void gemm_qkv_kernel(const float* __restrict__ X,
                                                       const float* __restrict__ Wq,
                                                       const float* __restrict__ Wk,
                                                       const float* __restrict__ Wv)
{
    const float* W = (blockIdx.z == 0) ? Wq : (blockIdx.z == 1 ? Wk : Wv);
    float* Out = g_qkv + (size_t)blockIdx.z * MM * CC;
    const int row0 = blockIdx.x * 64, col0 = blockIdx.y * 64;
    float acc[4][4] = {};
    gemm_tile_compute(X, W, acc, row0, col0);
    const int ty = threadIdx.x >> 4, tx = threadIdx.x & 15;
#pragma unroll
    for (int i = 0; i < 4; i++) {
        float4 v = make_float4(acc[i][0], acc[i][1], acc[i][2], acc[i][3]);
        *(float4*)(Out + (size_t)(row0 + ty*4 + i) * CC + col0 + tx * 4) = v;
    }
}

// ---------------- kernel 2: column sum-of-squares over T (partials) ----------------
__global__ __launch_bounds__(512) void sumsq_partial_kernel()
{
    const int ch = blockIdx.x, b = blockIdx.y, proj = blockIdx.z;
    const int c = threadIdx.x;
    const int trows = TT / NCHUNK;   // 128
    const float* p = g_qkv + ((size_t)proj * MM + (size_t)b * TT + (size_t)ch * trows) * CC;
    float s = 0.f;
#pragma unroll 4
    for (int t = 0; t < trows; t++) {
        float v = p[(size_t)t * CC + c];
        s += v * v;
    }
    g_partial[((proj * BB + b) * NCHUNK + ch) * CC + c] = s;
}

// ---------------- kernel 3: finalize inverse norms ----------------
__global__ __launch_bounds__(512) void inv_finalize_kernel()
{
    const int pb = blockIdx.x;       // proj*BB + b, 0..11
    const int c = threadIdx.x;
    float s = 0.f;
#pragma unroll
    for (int ch = 0; ch < NCHUNK; ch++)
        s += g_partial[(pb * NCHUNK + ch) * CC + c];
    g_inv[pb * CC + c] = rsqrtf(s * (1.0f / TT) + EPSN);
}

// ---------------- kernel 4: flash attention (fp32) ----------------
// Bq=64, Bkv=32, d=64; 256 threads; norm factors + softmax scale folded into loads.
__global__ __launch_bounds__(256) void attn_kernel()
{
    const int qt = blockIdx.x;            // 0..31
    const int bh = blockIdx.y;            // 0..31
    const int b = bh >> 3, h = bh & 7;

    const float* Qp = g_qkv + ((size_t)b * TT) * CC + h * DD;
    const float* Kp = g_qkv + (size_t)MM * CC + ((size_t)b * TT) * CC + h * DD;
    const float* Vp = g_qkv + 2ull * MM * CC + ((size_t)b * TT) * CC + h * DD;
    const float* invq = g_inv + (0 * BB + b) * CC + h * DD;
    const float* invk = g_inv + (1 * BB + b) * CC + h * DD;
    const float* invv = g_inv + (2 * BB + b) * CC + h * DD;

    __shared__ float Qs[64][68];   // [d][q]
    __shared__ float Ks[64][36];   // [d][kv]
    __shared__ float Vs[32][68];   // [kv][d]
    __shared__ float Ps[32][68];   // [kv][q]
    __shared__ float row_max[64], row_sum[64];

    const int tid = threadIdx.x;
    const int ty = tid >> 4, tx = tid & 15;
    const float scale = 0.125f;   // 1/sqrt(64)

    // load Q tile (transposed), scaled by invq * softmax scale
#pragma unroll
    for (int it = 0; it < 4; it++) {
        int l = tid + it * 256;           // 0..1023 float4
        int r = l >> 4, c4 = l & 15;
        float4 v = *(const float4*)(Qp + (size_t)(qt * 64 + r) * CC + c4 * 4);
        float4 s = *(const float4*)(invq + c4 * 4);
        Qs[c4*4+0][r] = v.x * s.x * scale;
        Qs[c4*4+1][r] = v.y * s.y * scale;
        Qs[c4*4+2][r] = v.z * s.z * scale;
        Qs[c4*4+3][r] = v.w * s.w * scale;
    }
    if (tid < 64) { row_max[tid] = -INFINITY; row_sum[tid] = 0.f; }

    float acc[4][4] = {};

    for (int kt = 0; kt < TT / 32; kt++) {
        __syncthreads();
        // load K (transposed) and V tiles, scaled by their inverse norms
#pragma unroll
        for (int it = 0; it < 2; it++) {
            int l = tid + it * 256;       // 0..511 float4
            int r = l >> 4, c4 = l & 15;
            float4 kv4 = *(const float4*)(Kp + (size_t)(kt * 32 + r) * CC + c4 * 4);
            float4 ks = *(const float4*)(invk + c4 * 4);
            Ks[c4*4+0][r] = kv4.x * ks.x;
            Ks[c4*4+1][r] = kv4.y * ks.y;
            Ks[c4*4+2][r] = kv4.z * ks.z;
            Ks[c4*4+3][r] = kv4.w * ks.w;
            float4 vv4 = *(const float4*)(Vp + (size_t)(kt * 32 + r) * CC + c4 * 4);
            float4 vs = *(const float4*)(invv + c4 * 4);
            float4 o;
            o.x = vv4.x * vs.x; o.y = vv4.y * vs.y;
            o.z = vv4.z * vs.z; o.w = vv4.w * vs.w;
            *(float4*)&Vs[r][c4 * 4] = o;
        }
        __syncthreads();

        // S = Q · K^T  (per-thread 4 q-rows x 2 kv-cols)
        float s[4][2] = {};
#pragma unroll
        for (int d = 0; d < 64; d++) {
            float4 a = *(const float4*)&Qs[d][ty * 4];
            float2 bq = *(const float2*)&Ks[d][tx * 2];
            s[0][0] += a.x * bq.x; s[0][1] += a.x * bq.y;
            s[1][0] += a.y * bq.x; s[1][1] += a.y * bq.y;
            s[2][0] += a.z * bq.x; s[2][1] += a.z * bq.y;
            s[3][0] += a.w * bq.x; s[3][1] += a.w * bq.y;
        }

        // online softmax: rows of a 16-lane group are convergent within a half-warp
        float mv[4], lv[4], fac[4];
#pragma unroll
        for (int i = 0; i < 4; i++) {
            float lm = fmaxf(s[i][0], s[i][1]);
#pragma unroll
            for (int off = 8; off; off >>= 1)
                lm = fmaxf(lm, __shfl_xor_sync(0xffffffffu, lm, off));
            float mold = row_max[ty * 4 + i];
            float mnew = fmaxf(mold, lm);
            fac[i] = __expf(mold - mnew);
            s[i][0] = __expf(s[i][0] - mnew);
            s[i][1] = __expf(s[i][1] - mnew);
            float ls = s[i][0] + s[i][1];
#pragma unroll
            for (int off = 8; off; off >>= 1)
                ls += __shfl_xor_sync(0xffffffffu, ls, off);
            mv[i] = mnew;
            lv[i] = row_sum[ty * 4 + i] * fac[i] + ls;
        }
        __syncwarp();
        if (tx == 0) {
#pragma unroll
            for (int i = 0; i < 4; i++) {
                row_max[ty * 4 + i] = mv[i];
                row_sum[ty * 4 + i] = lv[i];
            }
        }
        // rescale accumulators, stage P (transposed)
#pragma unroll
        for (int i = 0; i < 4; i++) {
            acc[i][0] *= fac[i]; acc[i][1] *= fac[i];
            acc[i][2] *= fac[i]; acc[i][3] *= fac[i];
            Ps[tx * 2 + 0][ty * 4 + i] = s[i][0];
            Ps[tx * 2 + 1][ty * 4 + i] = s[i][1];
        }
        __syncthreads();

        // O += P · V
#pragma unroll
        for (int kv = 0; kv < 32; kv++) {
            float4 p = *(const float4*)&Ps[kv][ty * 4];
            float4 v = *(const float4*)&Vs[kv][tx * 4];
            acc[0][0] += p.x*v.x; acc[0][1] += p.x*v.y; acc[0][2] += p.x*v.z; acc[0][3] += p.x*v.w;
            acc[1][0] += p.y*v.x; acc[1][1] += p.y*v.y; acc[1][2] += p.y*v.z; acc[1][3] += p.y*v.w;
            acc[2][0] += p.z*v.x; acc[2][1] += p.z*v.y; acc[2][2] += p.z*v.z; acc[2][3] += p.z*v.w;
            acc[3][0] += p.w*v.x; acc[3][1] += p.w*v.y; acc[3][2] += p.w*v.z; acc[3][3] += p.w*v.w;
        }
    }

    // normalize and write (row_sum last written before the Ps __syncthreads)
    float* Op = g_attn + ((size_t)b * TT + qt * 64) * CC + h * DD;
#pragma unroll
    for (int i = 0; i < 4; i++) {
        float il = 1.0f / row_sum[ty * 4 + i];
        float4 o = make_float4(acc[i][0] * il, acc[i][1] * il,
                               acc[i][2] * il, acc[i][3] * il);
        *(float4*)(Op + (size_t)(ty * 4 + i) * CC + tx * 4) = o;
    }
}

// ---------------- kernel 5: out-proj + bias + residual ----------------
__global__ __launch_bounds__(256) void gemm_out_kernel(const float* __restrict__ Wo,
                                                       const float* __restrict__ bo,
                                                       const float* __restrict__ residual,
                                                       float* __restrict__ Out)
{
    const int row0 = blockIdx.x * 64, col0 = blockIdx.y * 64;
    float acc[4][4] = {};
    gemm_tile_compute(g_attn, Wo, acc, row0, col0);
    const int ty = threadIdx.x >> 4, tx = threadIdx.x & 15;
    float4 bias = *(const float4*)(bo + col0 + tx * 4);
#pragma unroll
    for (int i = 0; i < 4; i++) {
        size_t off = (size_t)(row0 + ty*4 + i) * CC + col0 + tx * 4;
        float4 r = *(const float4*)(residual + off);
        float4 v = make_float4(acc[i][0] + bias.x + r.x,
                               acc[i][1] + bias.y + r.y,
                               acc[i][2] + bias.z + r.z,
                               acc[i][3] + bias.w + r.w);
        *(float4*)(Out + off) = v;
    }
}

// ---------------- launch ----------------
extern "C" void kernel_launch(void* const* d_in, const int* in_sizes, int n_in,
                              void* d_out, int out_size)
{
    (void)in_sizes; (void)n_in; (void)out_size;
    const float* X  = (const float*)d_in[0];
    const float* Wq = (const float*)d_in[1];
    const float* Wk = (const float*)d_in[2];
    const float* Wv = (const float*)d_in[3];
    const float* Wo = (const float*)d_in[4];
    const float* bo = (const float*)d_in[5];
    float* out = (float*)d_out;

    gemm_qkv_kernel<<<dim3(MM / 64, CC / 64, 3), 256>>>(X, Wq, Wk, Wv);
    sumsq_partial_kernel<<<dim3(NCHUNK, BB, 3), 512>>>();
    inv_finalize_kernel<<<dim3(3 * BB), 512>>>();
    attn_kernel<<<dim3(TT / 64, BB * HH), 256>>>();
    gemm_out_kernel<<<dim3(MM / 64, CC / 64), 256>>>(Wo, bo, X, out);
}

// round 12
// speedup vs baseline: 1.1074x; 1.1065x over previous
#include <cuda_runtime.h>
#include <math.h>

#define BB 4
#define TT 2048
#define CC 512
#define HH 8
#define DD 64
#define MM (BB*TT)          // 8192 rows
#define NCHUNK 16
#define EPSN 1e-4f

// ---------------- scratch (no allocation allowed) ----------------
__device__ float g_qkv[3u*MM*CC];          // Q,K,V projections (pre-scaled in place)
__device__ float g_attn[(size_t)MM*CC];    // attention output pre-Wo
__device__ float g_partial[3*BB*NCHUNK*CC];
__device__ float g_inv[3*BB*CC];           // rsqrt(mean_t x^2 + eps) per (proj,b,c)

// ---------------- shared 64x64x32 SGEMM tile ----------------
__device__ __forceinline__ void gemm_tile_compute(const float* __restrict__ A,
                                                  const float* __restrict__ W,
                                                  float acc[4][4],
                                                  int row0, int col0)
{
    __shared__ float As[32][64];   // [k][m] transposed
    __shared__ float Ws[32][64];   // [k][n]
    const int tid = threadIdx.x;
    const int ty = tid >> 4, tx = tid & 15;

    for (int kk = 0; kk < CC; kk += 32) {
#pragma unroll
        for (int it = 0; it < 2; it++) {
            int l = tid + it * 256;          // 0..511 float4 of A tile
            int r = l >> 3, c4 = l & 7;
            float4 v = *(const float4*)(A + (size_t)(row0 + r) * CC + kk + c4 * 4);
            As[c4*4+0][r] = v.x; As[c4*4+1][r] = v.y;
            As[c4*4+2][r] = v.z; As[c4*4+3][r] = v.w;
        }
#pragma unroll
        for (int it = 0; it < 2; it++) {
            int l = tid + it * 256;          // 0..511 float4 of W tile
            int r = l >> 4, c4 = l & 15;
            *(float4*)&Ws[r][c4*4] =
                *(const float4*)(W + (size_t)(kk + r) * CC + col0 + c4 * 4);
        }
        __syncthreads();
#pragma unroll
        for (int k = 0; k < 32; k++) {
            float4 a = *(const float4*)&As[k][ty * 4];
            float4 b = *(const float4*)&Ws[k][tx * 4];
            acc[0][0] += a.x*b.x; acc[0][1] += a.x*b.y; acc[0][2] += a.x*b.z; acc[0][3] += a.x*b.w;
            acc[1][0] += a.y*b.x; acc[1][1] += a.y*b.y; acc[1][2] += a.y*b.z; acc[1][3] += a.y*b.w;
            acc[2][0] += a.z*b.x; acc[2][1] += a.z*b.y; acc[2][2] += a.z*b.z; acc[2][3] += a.z*b.w;
            acc[3][0] += a.w*b.x; acc[3][1] += a.w*b.y; acc[3][2] += a.w*b.z; acc[3][3] += a.w*b.w;
        }
        __syncthreads();
    }
}

// ---------------- kernel 1: Q,K,V projections ----------------
__global__ __launch_bounds__(256) void gemm_qkv_kernel(const float* __restrict__ X,
                                                       const float* __restrict__ Wq,
                                                       const float* __restrict__ Wk,
                                                       const float* __restrict__ Wv)
{
    const float* W = (blockIdx.z == 0) ? Wq : (blockIdx.z == 1 ? Wk : Wv);
    float* Out = g_qkv + (size_t)blockIdx.z * MM * CC;
    const int row0 = blockIdx.x * 64, col0 = blockIdx.y * 64;
    float acc[4][4] = {};
    gemm_tile_compute(X, W, acc, row0, col0);
    const int ty = threadIdx.x >> 4, tx = threadIdx.x & 15;
#pragma unroll
    for (int i = 0; i < 4; i++) {
        float4 v = make_float4(acc[i][0], acc[i][1], acc[i][2], acc[i][3]);
        *(float4*)(Out + (size_t)(row0 + ty*4 + i) * CC + col0 + tx * 4) = v;
    }
}

// ---------------- kernel 2: column sum-of-squares over T (partials) ----------------
__global__ __launch_bounds__(512) void sumsq_partial_kernel()
{
    const int ch = blockIdx.x, b = blockIdx.y, proj = blockIdx.z;
    const int c = threadIdx.x;
    const int trows = TT / NCHUNK;   // 128
    const float* p = g_qkv + ((size_t)proj * MM + (size_t)b * TT + (size_t)ch * trows) * CC;
    float s = 0.f;
#pragma unroll 4
    for (int t = 0; t < trows; t++) {
        float v = p[(size_t)t * CC + c];
        s += v * v;
    }
    g_partial[((proj * BB + b) * NCHUNK + ch) * CC + c] = s;
}

// ---------------- kernel 3: finalize inverse norms ----------------
__global__ __launch_bounds__(512) void inv_finalize_kernel()
{
    const int pb = blockIdx.x;       // proj*BB + b, 0..11
    const int c = threadIdx.x;
    float s = 0.f;
#pragma unroll
    for (int ch = 0; ch < NCHUNK; ch++)
        s += g_partial[(pb * NCHUNK + ch) * CC + c];
    g_inv[pb * CC + c] = rsqrtf(s * (1.0f / TT) + EPSN);
}

// ---------------- kernel 3b: apply norms in place (fold 1/8 into Q) ----------------
__global__ __launch_bounds__(256) void scale_qkv_kernel()
{
    size_t gid = (size_t)blockIdx.x * 256 + threadIdx.x;  // one float4 each
    size_t flat = gid * 4;                                 // < 3*MM*CC
    int c  = (int)(flat % CC);
    int pb = (int)(flat / ((size_t)TT * CC));              // proj*BB + b
    float4 f = *(const float4*)(g_inv + pb * CC + c);
    if (pb < BB) { f.x *= 0.125f; f.y *= 0.125f; f.z *= 0.125f; f.w *= 0.125f; }
    float4 v = *(float4*)(g_qkv + flat);
    v.x *= f.x; v.y *= f.y; v.z *= f.z; v.w *= f.w;
    *(float4*)(g_qkv + flat) = v;
}

// ---------------- kernel 4: flash attention (fp32) ----------------
// Bq=64, Bkv=64, d=64; 256 threads; 4x4 micro-tiles in both matmuls;
// register prefetch of the next K/V tile; Q/K/V pre-scaled.
#define LDW 68
__global__ __launch_bounds__(256, 2) void attn_kernel()
{
    extern __shared__ float sm[];
    float* Qs = sm;                         // [64][LDW]  (d-major)
    float* Ks = sm + 64 * LDW;              // [64][LDW]  (d-major)
    float* Vs = sm + 2 * 64 * LDW;          // [64][LDW]  (kv-major)
    float* Ps = sm + 3 * 64 * LDW;          // [64][LDW]  (kv-major)
    float* row_max = sm + 4 * 64 * LDW;     // [64]
    float* row_sum = row_max + 64;          // [64]

    const int qt = blockIdx.x;              // 0..31
    const int bh = blockIdx.y;              // 0..31
    const int b = bh >> 3, h = bh & 7;

    const float* Qp = g_qkv + ((size_t)b * TT) * CC + h * DD;
    const float* Kp = g_qkv + (size_t)MM * CC + ((size_t)b * TT) * CC + h * DD;
    const float* Vp = g_qkv + 2ull * MM * CC + ((size_t)b * TT) * CC + h * DD;

    const int tid = threadIdx.x;
    const int ty = tid >> 4, tx = tid & 15;

    // load Q tile transposed (already scaled by invq/8)
#pragma unroll
    for (int it = 0; it < 4; it++) {
        int l = tid + it * 256;             // 0..1023 float4
        int r = l >> 4, c4 = l & 15;
        float4 v = *(const float4*)(Qp + (size_t)(qt * 64 + r) * CC + c4 * 4);
        Qs[(c4*4+0)*LDW + r] = v.x;
        Qs[(c4*4+1)*LDW + r] = v.y;
        Qs[(c4*4+2)*LDW + r] = v.z;
        Qs[(c4*4+3)*LDW + r] = v.w;
    }
    if (tid < 64) { row_max[tid] = -INFINITY; row_sum[tid] = 0.f; }

    // prefetch tile 0 into registers
    float4 kr[4], vr[4];
#pragma unroll
    for (int it = 0; it < 4; it++) {
        int l = tid + it * 256;
        int r = l >> 4, c4 = l & 15;
        kr[it] = *(const float4*)(Kp + (size_t)r * CC + c4 * 4);
        vr[it] = *(const float4*)(Vp + (size_t)r * CC + c4 * 4);
    }

    float acc[4][4] = {};

    for (int kt = 0; kt < TT / 64; kt++) {
        __syncthreads();                    // previous PV done with Ks/Vs/Ps
        // publish prefetched tile: K transposed to [d][kv], V as [kv][d]
#pragma unroll
        for (int it = 0; it < 4; it++) {
            int l = tid + it * 256;
            int r = l >> 4, c4 = l & 15;
            Ks[(c4*4+0)*LDW + r] = kr[it].x;
            Ks[(c4*4+1)*LDW + r] = kr[it].y;
            Ks[(c4*4+2)*LDW + r] = kr[it].z;
            Ks[(c4*4+3)*LDW + r] = kr[it].w;
            *(float4*)&Vs[r * LDW + c4 * 4] = vr[it];
        }
        __syncthreads();
        // issue prefetch for next tile; latency hides under S + PV compute
        if (kt + 1 < TT / 64) {
#pragma unroll
            for (int it = 0; it < 4; it++) {
                int l = tid + it * 256;
                int r = (kt + 1) * 64 + (l >> 4);
                int c4 = l & 15;
                kr[it] = *(const float4*)(Kp + (size_t)r * CC + c4 * 4);
                vr[it] = *(const float4*)(Vp + (size_t)r * CC + c4 * 4);
            }
        }

        // S = Q · K^T  (4 q-rows x 4 kv-cols per thread)
        float s[4][4] = {};
#pragma unroll
        for (int d = 0; d < 64; d++) {
            float4 a  = *(const float4*)&Qs[d * LDW + ty * 4];
            float4 bq = *(const float4*)&Ks[d * LDW + tx * 4];
            s[0][0] += a.x*bq.x; s[0][1] += a.x*bq.y; s[0][2] += a.x*bq.z; s[0][3] += a.x*bq.w;
            s[1][0] += a.y*bq.x; s[1][1] += a.y*bq.y; s[1][2] += a.y*bq.z; s[1][3] += a.y*bq.w;
            s[2][0] += a.z*bq.x; s[2][1] += a.z*bq.y; s[2][2] += a.z*bq.z; s[2][3] += a.z*bq.w;
            s[3][0] += a.w*bq.x; s[3][1] += a.w*bq.y; s[3][2] += a.w*bq.z; s[3][3] += a.w*bq.w;
        }

        // online softmax (16-lane row groups)
        float mv[4], lv[4], fac[4];
#pragma unroll
        for (int i = 0; i < 4; i++) {
            float lm = fmaxf(fmaxf(s[i][0], s[i][1]), fmaxf(s[i][2], s[i][3]));
#pragma unroll
            for (int off = 8; off; off >>= 1)
                lm = fmaxf(lm, __shfl_xor_sync(0xffffffffu, lm, off));
            float mold = row_max[ty * 4 + i];
            float mnew = fmaxf(mold, lm);
            fac[i] = __expf(mold - mnew);
            s[i][0] = __expf(s[i][0] - mnew);
            s[i][1] = __expf(s[i][1] - mnew);
            s[i][2] = __expf(s[i][2] - mnew);
            s[i][3] = __expf(s[i][3] - mnew);
            float ls = (s[i][0] + s[i][1]) + (s[i][2] + s[i][3]);
#pragma unroll
            for (int off = 8; off; off >>= 1)
                ls += __shfl_xor_sync(0xffffffffu, ls, off);
            mv[i] = mnew;
            lv[i] = row_sum[ty * 4 + i] * fac[i] + ls;
        }
        __syncwarp();
        if (tx == 0) {
#pragma unroll
            for (int i = 0; i < 4; i++) {
                row_max[ty * 4 + i] = mv[i];
                row_sum[ty * 4 + i] = lv[i];
            }
        }
        // rescale accumulators, stage P transposed [kv][q]
#pragma unroll
        for (int i = 0; i < 4; i++) {
            acc[i][0] *= fac[i]; acc[i][1] *= fac[i];
            acc[i][2] *= fac[i]; acc[i][3] *= fac[i];
#pragma unroll
            for (int j = 0; j < 4; j++)
                Ps[(tx * 4 + j) * LDW + ty * 4 + i] = s[i][j];
        }
        __syncthreads();

        // O += P · V
#pragma unroll
        for (int kv = 0; kv < 64; kv++) {
            float4 p = *(const float4*)&Ps[kv * LDW + ty * 4];
            float4 v = *(const float4*)&Vs[kv * LDW + tx * 4];
            acc[0][0] += p.x*v.x; acc[0][1] += p.x*v.y; acc[0][2] += p.x*v.z; acc[0][3] += p.x*v.w;
            acc[1][0] += p.y*v.x; acc[1][1] += p.y*v.y; acc[1][2] += p.y*v.z; acc[1][3] += p.y*v.w;
            acc[2][0] += p.z*v.x; acc[2][1] += p.z*v.y; acc[2][2] += p.z*v.z; acc[2][3] += p.z*v.w;
            acc[3][0] += p.w*v.x; acc[3][1] += p.w*v.y; acc[3][2] += p.w*v.z; acc[3][3] += p.w*v.w;
        }
    }

    // normalize and write
    float* Op = g_attn + ((size_t)b * TT + qt * 64) * CC + h * DD;
#pragma unroll
    for (int i = 0; i < 4; i++) {
        float il = 1.0f / row_sum[ty * 4 + i];
        float4 o = make_float4(acc[i][0] * il, acc[i][1] * il,
                               acc[i][2] * il, acc[i][3] * il);
        *(float4*)(Op + (size_t)(ty * 4 + i) * CC + tx * 4) = o;
    }
}

// ---------------- kernel 5: out-proj + bias + residual ----------------
__global__ __launch_bounds__(256) void gemm_out_kernel(const float* __restrict__ Wo,
                                                       const float* __restrict__ bo,
                                                       const float* __restrict__ residual,
                                                       float* __restrict__ Out)
{
    const int row0 = blockIdx.x * 64, col0 = blockIdx.y * 64;
    float acc[4][4] = {};
    gemm_tile_compute(g_attn, Wo, acc, row0, col0);
    const int ty = threadIdx.x >> 4, tx = threadIdx.x & 15;
    float4 bias = *(const float4*)(bo + col0 + tx * 4);
#pragma unroll
    for (int i = 0; i < 4; i++) {
        size_t off = (size_t)(row0 + ty*4 + i) * CC + col0 + tx * 4;
        float4 r = *(const float4*)(residual + off);
        float4 v = make_float4(acc[i][0] + bias.x + r.x,
                               acc[i][1] + bias.y + r.y,
                               acc[i][2] + bias.z + r.z,
                               acc[i][3] + bias.w + r.w);
        *(float4*)(Out + off) = v;
    }
}

// ---------------- launch ----------------
#define ATTN_SMEM ((4 * 64 * LDW + 128) * (int)sizeof(float))   // 70144 B

extern "C" void kernel_launch(void* const* d_in, const int* in_sizes, int n_in,
                              void* d_out, int out_size)
{
    (void)in_sizes; (void)n_in; (void)out_size;
    const float* X  = (const float*)d_in[0];
    const float* Wq = (const float*)d_in[1];
    const float* Wk = (const float*)d_in[2];
    const float* Wv = (const float*)d_in[3];
    const float* Wo = (const float*)d_in[4];
    const float* bo = (const float*)d_in[5];
    float* out = (float*)d_out;

    cudaFuncSetAttribute(attn_kernel,
                         cudaFuncAttributeMaxDynamicSharedMemorySize, ATTN_SMEM);

    gemm_qkv_kernel<<<dim3(MM / 64, CC / 64, 3), 256>>>(X, Wq, Wk, Wv);
    sumsq_partial_kernel<<<dim3(NCHUNK, BB, 3), 512>>>();
    inv_finalize_kernel<<<dim3(3 * BB), 512>>>();
    scale_qkv_kernel<<<(3u * MM * CC / 4) / 256, 256>>>();
    attn_kernel<<<dim3(TT / 64, BB * HH), 256, ATTN_SMEM>>>();
    gemm_out_kernel<<<dim3(MM / 64, CC / 64), 256>>>(Wo, bo, X, out);
}

// round 13
// speedup vs baseline: 2.9677x; 2.6798x over previous
#include <cuda_runtime.h>
#include <cuda_bf16.h>
#include <math.h>
#include <stdint.h>

#define BB 4
#define TT 2048
#define CC 512
#define HH 8
#define DD 64
#define MM (BB*TT)          // 8192 rows
#define NCHUNK 16
#define EPSN 1e-4f

// ---------------- scratch (no allocation allowed) ----------------
__device__ float g_qkv[(size_t)3*MM*CC];       // fp32 Q,K,V projections (for norms)
__device__ float g_partial[3*BB*NCHUNK*CC];
__device__ float g_inv[3*BB*CC];
__device__ __nv_bfloat16 g_x_h[(size_t)MM*CC],   g_x_l[(size_t)MM*CC];    // X split
__device__ __nv_bfloat16 g_w_h[(size_t)4*CC*CC], g_w_l[(size_t)4*CC*CC];  // Wq,Wk,Wv,Wo split
__device__ __nv_bfloat16 g_s_h[(size_t)3*MM*CC], g_s_l[(size_t)3*MM*CC];  // scaled Q,K,V split
__device__ __nv_bfloat16 g_a_h[(size_t)MM*CC],   g_a_l[(size_t)MM*CC];    // attn out split

// ---------------- PTX helpers ----------------
__device__ __forceinline__ uint32_t sm_u32(const void* p){
    return (uint32_t)__cvta_generic_to_shared(p);
}
__device__ __forceinline__ void ldm4(uint32_t* r, uint32_t a){
    asm volatile("ldmatrix.sync.aligned.m8n8.x4.shared.b16 {%0,%1,%2,%3}, [%4];"
        : "=r"(r[0]),"=r"(r[1]),"=r"(r[2]),"=r"(r[3]) : "r"(a));
}
__device__ __forceinline__ void ldm4t(uint32_t* r, uint32_t a){
    asm volatile("ldmatrix.sync.aligned.m8n8.x4.trans.shared.b16 {%0,%1,%2,%3}, [%4];"
        : "=r"(r[0]),"=r"(r[1]),"=r"(r[2]),"=r"(r[3]) : "r"(a));
}
__device__ __forceinline__ void mma16816(float* c, const uint32_t* a, uint32_t b0, uint32_t b1){
    asm volatile("mma.sync.aligned.m16n8k16.row.col.f32.bf16.bf16.f32 "
        "{%0,%1,%2,%3},{%4,%5,%6,%7},{%8,%9},{%0,%1,%2,%3};"
        : "+f"(c[0]),"+f"(c[1]),"+f"(c[2]),"+f"(c[3])
        : "r"(a[0]),"r"(a[1]),"r"(a[2]),"r"(a[3]),"r"(b0),"r"(b1));
}
__device__ __forceinline__ void cpasync16(uint32_t dst, const void* src){
    asm volatile("cp.async.ca.shared.global [%0], [%1], 16;" :: "r"(dst), "l"(src));
}
__device__ __forceinline__ void cpcommit(){ asm volatile("cp.async.commit_group;"); }
template<int N> __device__ __forceinline__ void cpwait(){
    asm volatile("cp.async.wait_group %0;" :: "n"(N));
}
__device__ __forceinline__ uint32_t packbf(float x, float y){
    __nv_bfloat162 t; t.x = __float2bfloat16(x); t.y = __float2bfloat16(y);
    return *(uint32_t*)&t;
}

// ---------------- split kernels ----------------
__global__ __launch_bounds__(256) void split_x_kernel(const float* __restrict__ src)
{
    size_t i = ((size_t)blockIdx.x * 256 + threadIdx.x) * 4;
    float4 v = *(const float4*)(src + i);
    __nv_bfloat162 h0,h1,l0,l1;
    h0.x = __float2bfloat16(v.x); l0.x = __float2bfloat16(v.x - __bfloat162float(h0.x));
    h0.y = __float2bfloat16(v.y); l0.y = __float2bfloat16(v.y - __bfloat162float(h0.y));
    h1.x = __float2bfloat16(v.z); l1.x = __float2bfloat16(v.z - __bfloat162float(h1.x));
    h1.y = __float2bfloat16(v.w); l1.y = __float2bfloat16(v.w - __bfloat162float(h1.y));
    *(__nv_bfloat162*)(g_x_h + i)     = h0; *(__nv_bfloat162*)(g_x_h + i + 2) = h1;
    *(__nv_bfloat162*)(g_x_l + i)     = l0; *(__nv_bfloat162*)(g_x_l + i + 2) = l1;
}
__global__ __launch_bounds__(256) void split_w_kernel(const float* __restrict__ src, int plane)
{
    size_t i = ((size_t)blockIdx.x * 256 + threadIdx.x) * 4;
    size_t o = (size_t)plane * CC * CC + i;
    float4 v = *(const float4*)(src + i);
    __nv_bfloat162 h0,h1,l0,l1;
    h0.x = __float2bfloat16(v.x); l0.x = __float2bfloat16(v.x - __bfloat162float(h0.x));
    h0.y = __float2bfloat16(v.y); l0.y = __float2bfloat16(v.y - __bfloat162float(h0.y));
    h1.x = __float2bfloat16(v.z); l1.x = __float2bfloat16(v.z - __bfloat162float(h1.x));
    h1.y = __float2bfloat16(v.w); l1.y = __float2bfloat16(v.w - __bfloat162float(h1.y));
    *(__nv_bfloat162*)(g_w_h + o)     = h0; *(__nv_bfloat162*)(g_w_h + o + 2) = h1;
    *(__nv_bfloat162*)(g_w_l + o)     = l0; *(__nv_bfloat162*)(g_w_l + o + 2) = l1;
}

// ---------------- mma GEMM: 64x64 CTA tile, K=512, split-bf16 ----------------
#define AP 40
#define BP 72
__global__ __launch_bounds__(256) void gemm_mma_kernel(
    int amode,                      // 0: A = g_x planes, 1: A = g_a planes
    int mode,                       // 0: out=g_qkv[z], B=W[z] | 1: out=d_out + bias + resid, B=W[3]
    const float* __restrict__ bias,
    const float* __restrict__ resid,
    float* __restrict__ outp)
{
    __shared__ __nv_bfloat16 sA[2][2][64*AP];
    __shared__ __nv_bfloat16 sB[2][2][32*BP];

    const int tid = threadIdx.x, w = tid >> 5, lane = tid & 31;
    const int wm = w & 3, wn = w >> 2;
    const int row0 = blockIdx.x * 64, col0 = blockIdx.y * 64;
    const int z = (mode == 0) ? blockIdx.z : 3;

    const __nv_bfloat16* Agh = amode ? g_a_h : g_x_h;
    const __nv_bfloat16* Agl = amode ? g_a_l : g_x_l;
    const __nv_bfloat16* Bgh = g_w_h + (size_t)z * CC * CC;
    const __nv_bfloat16* Bgl = g_w_l + (size_t)z * CC * CC;
    float* out = (mode == 0) ? (g_qkv + (size_t)blockIdx.z * MM * CC) : outp;

    const int ar = tid >> 2, ac = (tid & 3) * 8;     // A: 64 rows x 32
    const int br = tid >> 3, bc = (tid & 7) * 8;     // B: 32 rows x 64

    auto issue = [&](int c, int s){
        int kk = c * 32;
        cpasync16(sm_u32(&sA[s][0][ar*AP + ac]), Agh + (size_t)(row0+ar)*CC + kk + ac);
        cpasync16(sm_u32(&sA[s][1][ar*AP + ac]), Agl + (size_t)(row0+ar)*CC + kk + ac);
        cpasync16(sm_u32(&sB[s][0][br*BP + bc]), Bgh + (size_t)(kk+br)*CC + col0 + bc);
        cpasync16(sm_u32(&sB[s][1][br*BP + bc]), Bgl + (size_t)(kk+br)*CC + col0 + bc);
    };

    issue(0, 0); cpcommit();
    float acc[4][4] = {};

    for (int ch = 0; ch < 16; ch++){
        int s = ch & 1;
        if (ch < 15){ issue(ch+1, s^1); cpcommit(); cpwait<1>(); }
        else cpwait<0>();
        __syncthreads();
#pragma unroll
        for (int ks = 0; ks < 2; ks++){
            uint32_t ah[4], al[4];
            int aoff = (wm*16 + (lane & 15)) * AP + ks*16 + (lane >> 4) * 8;
            ldm4(ah, sm_u32(&sA[s][0][aoff]));
            ldm4(al, sm_u32(&sA[s][1][aoff]));
#pragma unroll
            for (int nt2 = 0; nt2 < 2; nt2++){
                int n0 = wn*32 + nt2*16;
                int boff = (ks*16 + (lane & 7) + ((lane >> 3) & 1)*8) * BP
                         + n0 + (lane >> 4) * 8;
                uint32_t bh4[4], bl4[4];
                ldm4t(bh4, sm_u32(&sB[s][0][boff]));
                ldm4t(bl4, sm_u32(&sB[s][1][boff]));
                int nt = nt2*2;
                mma16816(acc[nt],   ah, bh4[0], bh4[1]);
                mma16816(acc[nt],   ah, bl4[0], bl4[1]);
                mma16816(acc[nt],   al, bh4[0], bh4[1]);
                mma16816(acc[nt+1], ah, bh4[2], bh4[3]);
                mma16816(acc[nt+1], ah, bl4[2], bl4[3]);
                mma16816(acc[nt+1], al, bh4[2], bh4[3]);
            }
        }
        __syncthreads();
    }

    const int r0 = row0 + wm*16 + (lane >> 2);
#pragma unroll
    for (int nt = 0; nt < 4; nt++){
        int c0 = col0 + wn*32 + nt*8 + (lane & 3)*2;
        size_t o0 = (size_t)r0*CC + c0, o1 = (size_t)(r0+8)*CC + c0;
        if (mode == 0){
            *(float2*)(out + o0) = make_float2(acc[nt][0], acc[nt][1]);
            *(float2*)(out + o1) = make_float2(acc[nt][2], acc[nt][3]);
        } else {
            float2 bi = *(const float2*)(bias + c0);
            float2 ra = *(const float2*)(resid + o0);
            float2 rb = *(const float2*)(resid + o1);
            *(float2*)(out + o0) = make_float2(acc[nt][0]+bi.x+ra.x, acc[nt][1]+bi.y+ra.y);
            *(float2*)(out + o1) = make_float2(acc[nt][2]+bi.x+rb.x, acc[nt][3]+bi.y+rb.y);
        }
    }
}

// ---------------- norms (unchanged math, read fp32 g_qkv) ----------------
__global__ __launch_bounds__(512) void sumsq_partial_kernel()
{
    const int ch = blockIdx.x, b = blockIdx.y, proj = blockIdx.z;
    const int c = threadIdx.x;
    const int trows = TT / NCHUNK;
    const float* p = g_qkv + ((size_t)proj * MM + (size_t)b * TT + (size_t)ch * trows) * CC;
    float s = 0.f;
#pragma unroll 4
    for (int t = 0; t < trows; t++){ float v = p[(size_t)t * CC + c]; s += v * v; }
    g_partial[((proj * BB + b) * NCHUNK + ch) * CC + c] = s;
}
__global__ __launch_bounds__(512) void inv_finalize_kernel()
{
    const int pb = blockIdx.x;
    const int c = threadIdx.x;
    float s = 0.f;
#pragma unroll
    for (int ch = 0; ch < NCHUNK; ch++) s += g_partial[(pb * NCHUNK + ch) * CC + c];
    g_inv[pb * CC + c] = rsqrtf(s * (1.0f / TT) + EPSN);
}

// ---------------- scale (inv norms, 1/8 into Q) + split to bf16 planes ----------------
__global__ __launch_bounds__(256) void scale_split_kernel()
{
    size_t gid = (size_t)blockIdx.x * 256 + threadIdx.x;
    size_t flat = gid * 4;
    int c  = (int)(flat % CC);
    int pb = (int)(flat / ((size_t)TT * CC));
    float4 f = *(const float4*)(g_inv + pb * CC + c);
    if (pb < BB){ f.x *= 0.125f; f.y *= 0.125f; f.z *= 0.125f; f.w *= 0.125f; }
    float4 v = *(const float4*)(g_qkv + flat);
    v.x *= f.x; v.y *= f.y; v.z *= f.z; v.w *= f.w;
    __nv_bfloat162 h0,h1,l0,l1;
    h0.x = __float2bfloat16(v.x); l0.x = __float2bfloat16(v.x - __bfloat162float(h0.x));
    h0.y = __float2bfloat16(v.y); l0.y = __float2bfloat16(v.y - __bfloat162float(h0.y));
    h1.x = __float2bfloat16(v.z); l1.x = __float2bfloat16(v.z - __bfloat162float(h1.x));
    h1.y = __float2bfloat16(v.w); l1.y = __float2bfloat16(v.w - __bfloat162float(h1.y));
    *(__nv_bfloat162*)(g_s_h + flat)     = h0; *(__nv_bfloat162*)(g_s_h + flat + 2) = h1;
    *(__nv_bfloat162*)(g_s_l + flat)     = l0; *(__nv_bfloat162*)(g_s_l + flat + 2) = l1;
}

// ---------------- flash attention, split-bf16 mma ----------------
// Bq=128 (8 warps x m16), Bkv=64, d=64. KV double-buffered via cp.async.
#define ATP 72
#define AT_SMEM ((2*128*ATP + 2*4*64*ATP) * 2)   // 110592 bytes
__global__ __launch_bounds__(256, 2) void attn_mma_kernel()
{
    extern __shared__ __nv_bfloat16 smem_bf[];
    __nv_bfloat16* sQh = smem_bf;
    __nv_bfloat16* sQl = smem_bf + 128*ATP;
    __nv_bfloat16* sKV = smem_bf + 2*128*ATP;    // [stage][4 planes][64*ATP]

    const int tid = threadIdx.x, w = tid >> 5, lane = tid & 31;
    const int qt = blockIdx.x, bhid = blockIdx.y;
    const int b = bhid >> 3, h = bhid & 7;

    const size_t baseq = ((size_t)b*TT + (size_t)qt*128) * CC + h*DD;
    const size_t basek = ((size_t)b*TT) * CC + h*DD;
    const __nv_bfloat16* Qh_g = g_s_h + baseq;
    const __nv_bfloat16* Ql_g = g_s_l + baseq;
    const __nv_bfloat16* Kh_g = g_s_h + (size_t)MM*CC   + basek;
    const __nv_bfloat16* Kl_g = g_s_l + (size_t)MM*CC   + basek;
    const __nv_bfloat16* Vh_g = g_s_h + (size_t)2*MM*CC + basek;
    const __nv_bfloat16* Vl_g = g_s_l + (size_t)2*MM*CC + basek;

    // stage Q (plain vector loads)
#pragma unroll
    for (int it = 0; it < 4; it++){
        int idx = tid + it * 256;               // 0..1023
        int r = idx >> 3, cseg = (idx & 7) * 8;
        *(uint4*)&sQh[r*ATP + cseg] = *(const uint4*)(Qh_g + (size_t)r*CC + cseg);
        *(uint4*)&sQl[r*ATP + cseg] = *(const uint4*)(Ql_g + (size_t)r*CC + cseg);
    }

    auto issueKV = [&](int kt, int s){
        __nv_bfloat16* dst = sKV + (size_t)s * (4*64*ATP);
#pragma unroll
        for (int j = 0; j < 2; j++){
            int idx = tid*2 + j;                // 0..511
            int r = idx >> 3, cseg = (idx & 7) * 8;
            size_t g = (size_t)(kt*64 + r) * CC + cseg;
            int so = r*ATP + cseg;
            cpasync16(sm_u32(&dst[0*64*ATP + so]), Kh_g + g);
            cpasync16(sm_u32(&dst[1*64*ATP + so]), Kl_g + g);
            cpasync16(sm_u32(&dst[2*64*ATP + so]), Vh_g + g);
            cpasync16(sm_u32(&dst[3*64*ATP + so]), Vl_g + g);
        }
    };

    issueKV(0, 0); cpcommit();

    float o[8][4] = {};
    float st_m[2] = {-INFINITY, -INFINITY};
    float st_l[2] = {0.f, 0.f};

    for (int kt = 0; kt < 32; kt++){
        int s = kt & 1;
        if (kt < 31){ issueKV(kt+1, s^1); cpcommit(); cpwait<1>(); }
        else cpwait<0>();
        __syncthreads();
        __nv_bfloat16* Kh = sKV + (size_t)s * (4*64*ATP);
        __nv_bfloat16* Kl = Kh + 64*ATP;
        __nv_bfloat16* Vh = Kl + 64*ATP;
        __nv_bfloat16* Vl = Vh + 64*ATP;

        // ---- S = Q K^T ----
        float sacc[8][4] = {};
#pragma unroll
        for (int ks = 0; ks < 4; ks++){         // d chunks of 16
            uint32_t ah[4], al[4];
            int aoff = (w*16 + (lane & 15)) * ATP + ks*16 + (lane >> 4) * 8;
            ldm4(ah, sm_u32(&sQh[aoff]));
            ldm4(al, sm_u32(&sQl[aoff]));
#pragma unroll
            for (int nt2 = 0; nt2 < 4; nt2++){  // kv chunks of 16
                int koff = (nt2*16 + (lane & 7) + (lane >> 4)*8) * ATP
                         + ks*16 + ((lane >> 3) & 1)*8;
                uint32_t bh4[4], bl4[4];
                ldm4(bh4, sm_u32(&Kh[koff]));
                ldm4(bl4, sm_u32(&Kl[koff]));
                int nt = nt2*2;
                mma16816(sacc[nt],   ah, bh4[0], bh4[1]);
                mma16816(sacc[nt],   ah, bl4[0], bl4[1]);
                mma16816(sacc[nt],   al, bh4[0], bh4[1]);
                mma16816(sacc[nt+1], ah, bh4[2], bh4[3]);
                mma16816(sacc[nt+1], ah, bl4[2], bl4[3]);
                mma16816(sacc[nt+1], al, bh4[2], bh4[3]);
            }
        }

        // ---- online softmax (rows z=lane/4 and z+8; cols across 4-lane group) ----
        float lm0 = -INFINITY, lm1 = -INFINITY;
#pragma unroll
        for (int nt = 0; nt < 8; nt++){
            lm0 = fmaxf(lm0, fmaxf(sacc[nt][0], sacc[nt][1]));
            lm1 = fmaxf(lm1, fmaxf(sacc[nt][2], sacc[nt][3]));
        }
        lm0 = fmaxf(lm0, __shfl_xor_sync(0xffffffffu, lm0, 1));
        lm0 = fmaxf(lm0, __shfl_xor_sync(0xffffffffu, lm0, 2));
        lm1 = fmaxf(lm1, __shfl_xor_sync(0xffffffffu, lm1, 1));
        lm1 = fmaxf(lm1, __shfl_xor_sync(0xffffffffu, lm1, 2));
        float mn0 = fmaxf(st_m[0], lm0), mn1 = fmaxf(st_m[1], lm1);
        float f0 = __expf(st_m[0] - mn0), f1 = __expf(st_m[1] - mn1);
        st_m[0] = mn0; st_m[1] = mn1;
        float ls0 = 0.f, ls1 = 0.f;
#pragma unroll
        for (int nt = 0; nt < 8; nt++){
            sacc[nt][0] = __expf(sacc[nt][0] - mn0);
            sacc[nt][1] = __expf(sacc[nt][1] - mn0);
            sacc[nt][2] = __expf(sacc[nt][2] - mn1);
            sacc[nt][3] = __expf(sacc[nt][3] - mn1);
            ls0 += sacc[nt][0] + sacc[nt][1];
            ls1 += sacc[nt][2] + sacc[nt][3];
        }
        ls0 += __shfl_xor_sync(0xffffffffu, ls0, 1);
        ls0 += __shfl_xor_sync(0xffffffffu, ls0, 2);
        ls1 += __shfl_xor_sync(0xffffffffu, ls1, 1);
        ls1 += __shfl_xor_sync(0xffffffffu, ls1, 2);
        st_l[0] = st_l[0]*f0 + ls0; st_l[1] = st_l[1]*f1 + ls1;
#pragma unroll
        for (int nt = 0; nt < 8; nt++){
            o[nt][0] *= f0; o[nt][1] *= f0; o[nt][2] *= f1; o[nt][3] *= f1;
        }

        // ---- O += P V  (P from c-frags -> split a-frags, register-local) ----
#pragma unroll
        for (int ks = 0; ks < 4; ks++){         // kv chunks of 16
            uint32_t pah[4], pal[4];
            {
                float p0 = sacc[2*ks][0],   p1 = sacc[2*ks][1];
                float p2 = sacc[2*ks][2],   p3 = sacc[2*ks][3];
                float q0 = sacc[2*ks+1][0], q1 = sacc[2*ks+1][1];
                float q2 = sacc[2*ks+1][2], q3 = sacc[2*ks+1][3];
                __nv_bfloat16 hp0 = __float2bfloat16(p0), hp1 = __float2bfloat16(p1);
                __nv_bfloat16 hp2 = __float2bfloat16(p2), hp3 = __float2bfloat16(p3);
                __nv_bfloat16 hq0 = __float2bfloat16(q0), hq1 = __float2bfloat16(q1);
                __nv_bfloat16 hq2 = __float2bfloat16(q2), hq3 = __float2bfloat16(q3);
                pah[0] = packbf(p0, p1); pah[1] = packbf(p2, p3);
                pah[2] = packbf(q0, q1); pah[3] = packbf(q2, q3);
                pal[0] = packbf(p0 - __bfloat162float(hp0), p1 - __bfloat162float(hp1));
                pal[1] = packbf(p2 - __bfloat162float(hp2), p3 - __bfloat162float(hp3));
                pal[2] = packbf(q0 - __bfloat162float(hq0), q1 - __bfloat162float(hq1));
                pal[3] = packbf(q2 - __bfloat162float(hq2), q3 - __bfloat162float(hq3));
            }
#pragma unroll
            for (int nt2 = 0; nt2 < 4; nt2++){  // d chunks of 16
                int voff = (ks*16 + (lane & 7) + ((lane >> 3) & 1)*8) * ATP
                         + nt2*16 + (lane >> 4)*8;
                uint32_t vh4[4], vl4[4];
                ldm4t(vh4, sm_u32(&Vh[voff]));
                ldm4t(vl4, sm_u32(&Vl[voff]));
                int nt = nt2*2;
                mma16816(o[nt],   pah, vh4[0], vh4[1]);
                mma16816(o[nt],   pah, vl4[0], vl4[1]);
                mma16816(o[nt],   pal, vh4[0], vh4[1]);
                mma16816(o[nt+1], pah, vh4[2], vh4[3]);
                mma16816(o[nt+1], pah, vl4[2], vl4[3]);
                mma16816(o[nt+1], pal, vh4[2], vh4[3]);
            }
        }
        __syncthreads();   // all warps done reading this stage before it is overwritten
    }

    // ---- epilogue: normalize, split, write bf16 planes ----
    float il0 = 1.0f / st_l[0], il1 = 1.0f / st_l[1];
    int q0 = qt*128 + w*16 + (lane >> 2);
    size_t ob0 = ((size_t)b*TT + q0) * CC + h*DD;
    size_t ob1 = ob0 + (size_t)8*CC;
#pragma unroll
    for (int nt = 0; nt < 8; nt++){
        int c0 = nt*8 + (lane & 3)*2;
        float x0 = o[nt][0]*il0, x1 = o[nt][1]*il0;
        float y0 = o[nt][2]*il1, y1 = o[nt][3]*il1;
        __nv_bfloat162 xh, xl, yh, yl;
        xh.x = __float2bfloat16(x0); xl.x = __float2bfloat16(x0 - __bfloat162float(xh.x));
        xh.y = __float2bfloat16(x1); xl.y = __float2bfloat16(x1 - __bfloat162float(xh.y));
        yh.x = __float2bfloat16(y0); yl.x = __float2bfloat16(y0 - __bfloat162float(yh.x));
        yh.y = __float2bfloat16(y1); yl.y = __float2bfloat16(y1 - __bfloat162float(yh.y));
        *(__nv_bfloat162*)(g_a_h + ob0 + c0) = xh;
        *(__nv_bfloat162*)(g_a_l + ob0 + c0) = xl;
        *(__nv_bfloat162*)(g_a_h + ob1 + c0) = yh;
        *(__nv_bfloat162*)(g_a_l + ob1 + c0) = yl;
    }
}

// ---------------- launch ----------------
extern "C" void kernel_launch(void* const* d_in, const int* in_sizes, int n_in,
                              void* d_out, int out_size)
{
    (void)in_sizes; (void)n_in; (void)out_size;
    const float* X  = (const float*)d_in[0];
    const float* Wq = (const float*)d_in[1];
    const float* Wk = (const float*)d_in[2];
    const float* Wv = (const float*)d_in[3];
    const float* Wo = (const float*)d_in[4];
    const float* bo = (const float*)d_in[5];
    float* out = (float*)d_out;

    cudaFuncSetAttribute(attn_mma_kernel,
                         cudaFuncAttributeMaxDynamicSharedMemorySize, AT_SMEM);

    split_x_kernel<<<(size_t)MM*CC/1024, 256>>>(X);
    split_w_kernel<<<CC*CC/1024, 256>>>(Wq, 0);
    split_w_kernel<<<CC*CC/1024, 256>>>(Wk, 1);
    split_w_kernel<<<CC*CC/1024, 256>>>(Wv, 2);
    split_w_kernel<<<CC*CC/1024, 256>>>(Wo, 3);
    gemm_mma_kernel<<<dim3(MM/64, CC/64, 3), 256>>>(0, 0, nullptr, nullptr, nullptr);
    sumsq_partial_kernel<<<dim3(NCHUNK, BB, 3), 512>>>();
    inv_finalize_kernel<<<dim3(3*BB), 512>>>();
    scale_split_kernel<<<(3u*MM*CC/4)/256, 256>>>();
    attn_mma_kernel<<<dim3(TT/128, BB*HH), 256, AT_SMEM>>>();
    gemm_mma_kernel<<<dim3(MM/64, CC/64, 1), 256>>>(1, 1, bo, X, out);
}

// round 15
// speedup vs baseline: 3.1433x; 1.0592x over previous
#include <cuda_runtime.h>
#include <cuda_bf16.h>
#include <math.h>
#include <stdint.h>

#define BB 4
#define TT 2048
#define CC 512
#define HH 8
#define DD 64
#define MM (BB*TT)          // 8192 rows
#define NCHUNK 16
#define EPSN 1e-4f

// ---------------- scratch (no allocation allowed) ----------------
__device__ float g_qkv[(size_t)3*MM*CC];       // fp32 Q,K,V projections (for norms)
__device__ float g_partial[3*BB*NCHUNK*CC];
__device__ float g_inv[3*BB*CC];
__device__ __nv_bfloat16 g_x_h[(size_t)MM*CC],   g_x_l[(size_t)MM*CC];    // X split
__device__ __nv_bfloat16 g_w_h[(size_t)4*CC*CC], g_w_l[(size_t)4*CC*CC];  // Wq,Wk,Wv,Wo split
__device__ __nv_bfloat16 g_s_h[(size_t)3*MM*CC], g_s_l[(size_t)3*MM*CC];  // scaled Q,K,V split
__device__ __nv_bfloat16 g_a_h[(size_t)MM*CC],   g_a_l[(size_t)MM*CC];    // attn out split

// ---------------- PTX helpers ----------------
__device__ __forceinline__ uint32_t sm_u32(const void* p){
    return (uint32_t)__cvta_generic_to_shared(p);
}
__device__ __forceinline__ void ldm4(uint32_t* r, uint32_t a){
    asm volatile("ldmatrix.sync.aligned.m8n8.x4.shared.b16 {%0,%1,%2,%3}, [%4];"
        : "=r"(r[0]),"=r"(r[1]),"=r"(r[2]),"=r"(r[3]) : "r"(a));
}
__device__ __forceinline__ void ldm4t(uint32_t* r, uint32_t a){
    asm volatile("ldmatrix.sync.aligned.m8n8.x4.trans.shared.b16 {%0,%1,%2,%3}, [%4];"
        : "=r"(r[0]),"=r"(r[1]),"=r"(r[2]),"=r"(r[3]) : "r"(a));
}
__device__ __forceinline__ void mma16816(float* c, const uint32_t* a, uint32_t b0, uint32_t b1){
    asm volatile("mma.sync.aligned.m16n8k16.row.col.f32.bf16.bf16.f32 "
        "{%0,%1,%2,%3},{%4,%5,%6,%7},{%8,%9},{%0,%1,%2,%3};"
        : "+f"(c[0]),"+f"(c[1]),"+f"(c[2]),"+f"(c[3])
        : "r"(a[0]),"r"(a[1]),"r"(a[2]),"r"(a[3]),"r"(b0),"r"(b1));
}
__device__ __forceinline__ void cpasync16(uint32_t dst, const void* src){
    asm volatile("cp.async.ca.shared.global [%0], [%1], 16;" :: "r"(dst), "l"(src));
}
__device__ __forceinline__ void cpcommit(){ asm volatile("cp.async.commit_group;"); }
template<int N> __device__ __forceinline__ void cpwait(){
    asm volatile("cp.async.wait_group %0;" :: "n"(N));
}
__device__ __forceinline__ uint32_t packbf(float x, float y){
    __nv_bfloat162 t; t.x = __float2bfloat16(x); t.y = __float2bfloat16(y);
    return *(uint32_t*)&t;
}

// ---------------- split kernels ----------------
__global__ __launch_bounds__(256) void split_x_kernel(const float* __restrict__ src)
{
    size_t i = ((size_t)blockIdx.x * 256 + threadIdx.x) * 4;
    float4 v = *(const float4*)(src + i);
    __nv_bfloat162 h0,h1,l0,l1;
    h0.x = __float2bfloat16(v.x); l0.x = __float2bfloat16(v.x - __bfloat162float(h0.x));
    h0.y = __float2bfloat16(v.y); l0.y = __float2bfloat16(v.y - __bfloat162float(h0.y));
    h1.x = __float2bfloat16(v.z); l1.x = __float2bfloat16(v.z - __bfloat162float(h1.x));
    h1.y = __float2bfloat16(v.w); l1.y = __float2bfloat16(v.w - __bfloat162float(h1.y));
    *(__nv_bfloat162*)(g_x_h + i)     = h0; *(__nv_bfloat162*)(g_x_h + i + 2) = h1;
    *(__nv_bfloat162*)(g_x_l + i)     = l0; *(__nv_bfloat162*)(g_x_l + i + 2) = l1;
}
// all 4 weight matrices in one launch: plane = blockIdx.y
__global__ __launch_bounds__(256) void split_w4_kernel(
    const float* __restrict__ w0, const float* __restrict__ w1,
    const float* __restrict__ w2, const float* __restrict__ w3)
{
    const int plane = blockIdx.y;
    const float* src = (plane == 0) ? w0 : (plane == 1) ? w1 : (plane == 2) ? w2 : w3;
    size_t i = ((size_t)blockIdx.x * 256 + threadIdx.x) * 4;
    size_t o = (size_t)plane * CC * CC + i;
    float4 v = *(const float4*)(src + i);
    __nv_bfloat162 h0,h1,l0,l1;
    h0.x = __float2bfloat16(v.x); l0.x = __float2bfloat16(v.x - __bfloat162float(h0.x));
    h0.y = __float2bfloat16(v.y); l0.y = __float2bfloat16(v.y - __bfloat162float(h0.y));
    h1.x = __float2bfloat16(v.z); l1.x = __float2bfloat16(v.z - __bfloat162float(h1.x));
    h1.y = __float2bfloat16(v.w); l1.y = __float2bfloat16(v.w - __bfloat162float(h1.y));
    *(__nv_bfloat162*)(g_w_h + o)     = h0; *(__nv_bfloat162*)(g_w_h + o + 2) = h1;
    *(__nv_bfloat162*)(g_w_l + o)     = l0; *(__nv_bfloat162*)(g_w_l + o + 2) = l1;
}

// ---------------- mma GEMM: 64x64 CTA tile, K=512, split-bf16 ----------------
#define AP 40
#define BP 72
__global__ __launch_bounds__(256) void gemm_mma_kernel(
    int amode,                      // 0: A = g_x planes, 1: A = g_a planes
    int mode,                       // 0: out=g_qkv[z], B=W[z] | 1: out=d_out + bias + resid, B=W[3]
    const float* __restrict__ bias,
    const float* __restrict__ resid,
    float* __restrict__ outp)
{
    __shared__ __nv_bfloat16 sA[2][2][64*AP];
    __shared__ __nv_bfloat16 sB[2][2][32*BP];

    const int tid = threadIdx.x, w = tid >> 5, lane = tid & 31;
    const int wm = w & 3, wn = w >> 2;
    const int row0 = blockIdx.x * 64, col0 = blockIdx.y * 64;
    const int z = (mode == 0) ? blockIdx.z : 3;

    const __nv_bfloat16* Agh = amode ? g_a_h : g_x_h;
    const __nv_bfloat16* Agl = amode ? g_a_l : g_x_l;
    const __nv_bfloat16* Bgh = g_w_h + (size_t)z * CC * CC;
    const __nv_bfloat16* Bgl = g_w_l + (size_t)z * CC * CC;
    float* out = (mode == 0) ? (g_qkv + (size_t)blockIdx.z * MM * CC) : outp;

    const int ar = tid >> 2, ac = (tid & 3) * 8;     // A: 64 rows x 32
    const int br = tid >> 3, bc = (tid & 7) * 8;     // B: 32 rows x 64

    auto issue = [&](int c, int s){
        int kk = c * 32;
        cpasync16(sm_u32(&sA[s][0][ar*AP + ac]), Agh + (size_t)(row0+ar)*CC + kk + ac);
        cpasync16(sm_u32(&sA[s][1][ar*AP + ac]), Agl + (size_t)(row0+ar)*CC + kk + ac);
        cpasync16(sm_u32(&sB[s][0][br*BP + bc]), Bgh + (size_t)(kk+br)*CC + col0 + bc);
        cpasync16(sm_u32(&sB[s][1][br*BP + bc]), Bgl + (size_t)(kk+br)*CC + col0 + bc);
    };

    issue(0, 0); cpcommit();
    float acc[4][4] = {};

    for (int ch = 0; ch < 16; ch++){
        int s = ch & 1;
        if (ch < 15){ issue(ch+1, s^1); cpcommit(); cpwait<1>(); }
        else cpwait<0>();
        __syncthreads();
#pragma unroll
        for (int ks = 0; ks < 2; ks++){
            uint32_t ah[4], al[4];
            int aoff = (wm*16 + (lane & 15)) * AP + ks*16 + (lane >> 4) * 8;
            ldm4(ah, sm_u32(&sA[s][0][aoff]));
            ldm4(al, sm_u32(&sA[s][1][aoff]));
#pragma unroll
            for (int nt2 = 0; nt2 < 2; nt2++){
                int n0 = wn*32 + nt2*16;
                int boff = (ks*16 + (lane & 7) + ((lane >> 3) & 1)*8) * BP
                         + n0 + (lane >> 4) * 8;
                uint32_t bh4[4], bl4[4];
                ldm4t(bh4, sm_u32(&sB[s][0][boff]));
                ldm4t(bl4, sm_u32(&sB[s][1][boff]));
                int nt = nt2*2;
                mma16816(acc[nt],   ah, bh4[0], bh4[1]);
                mma16816(acc[nt],   ah, bl4[0], bl4[1]);
                mma16816(acc[nt],   al, bh4[0], bh4[1]);
                mma16816(acc[nt+1], ah, bh4[2], bh4[3]);
                mma16816(acc[nt+1], ah, bl4[2], bl4[3]);
                mma16816(acc[nt+1], al, bh4[2], bh4[3]);
            }
        }
        __syncthreads();
    }

    const int r0 = row0 + wm*16 + (lane >> 2);
#pragma unroll
    for (int nt = 0; nt < 4; nt++){
        int c0 = col0 + wn*32 + nt*8 + (lane & 3)*2;
        size_t o0 = (size_t)r0*CC + c0, o1 = (size_t)(r0+8)*CC + c0;
        if (mode == 0){
            *(float2*)(out + o0) = make_float2(acc[nt][0], acc[nt][1]);
            *(float2*)(out + o1) = make_float2(acc[nt][2], acc[nt][3]);
        } else {
            float2 bi = *(const float2*)(bias + c0);
            float2 ra = *(const float2*)(resid + o0);
            float2 rb = *(const float2*)(resid + o1);
            *(float2*)(out + o0) = make_float2(acc[nt][0]+bi.x+ra.x, acc[nt][1]+bi.y+ra.y);
            *(float2*)(out + o1) = make_float2(acc[nt][2]+bi.x+rb.x, acc[nt][3]+bi.y+rb.y);
        }
    }
}

// ---------------- norms (read fp32 g_qkv) ----------------
__global__ __launch_bounds__(512) void sumsq_partial_kernel()
{
    const int ch = blockIdx.x, b = blockIdx.y, proj = blockIdx.z;
    const int c = threadIdx.x;
    const int trows = TT / NCHUNK;
    const float* p = g_qkv + ((size_t)proj * MM + (size_t)b * TT + (size_t)ch * trows) * CC;
    float s = 0.f;
#pragma unroll 4
    for (int t = 0; t < trows; t++){ float v = p[(size_t)t * CC + c]; s += v * v; }
    g_partial[((proj * BB + b) * NCHUNK + ch) * CC + c] = s;
}
__global__ __launch_bounds__(512) void inv_finalize_kernel()
{
    const int pb = blockIdx.x;
    const int c = threadIdx.x;
    float s = 0.f;
#pragma unroll
    for (int ch = 0; ch < NCHUNK; ch++) s += g_partial[(pb * NCHUNK + ch) * CC + c];
    g_inv[pb * CC + c] = rsqrtf(s * (1.0f / TT) + EPSN);
}

// ---------------- scale (inv norms; 0.125*log2e into Q for exp2 softmax) + split ----------------
#define QSCALE (0.125f * 1.4426950408889634f)
__global__ __launch_bounds__(256) void scale_split_kernel()
{
    size_t gid = (size_t)blockIdx.x * 256 + threadIdx.x;
    size_t flat = gid * 4;
    int c  = (int)(flat % CC);
    int pb = (int)(flat / ((size_t)TT * CC));
    float4 f = *(const float4*)(g_inv + pb * CC + c);
    if (pb < BB){ f.x *= QSCALE; f.y *= QSCALE; f.z *= QSCALE; f.w *= QSCALE; }
    float4 v = *(const float4*)(g_qkv + flat);
    v.x *= f.x; v.y *= f.y; v.z *= f.z; v.w *= f.w;
    __nv_bfloat162 h0,h1,l0,l1;
    h0.x = __float2bfloat16(v.x); l0.x = __float2bfloat16(v.x - __bfloat162float(h0.x));
    h0.y = __float2bfloat16(v.y); l0.y = __float2bfloat16(v.y - __bfloat162float(h0.y));
    h1.x = __float2bfloat16(v.z); l1.x = __float2bfloat16(v.z - __bfloat162float(h1.x));
    h1.y = __float2bfloat16(v.w); l1.y = __float2bfloat16(v.w - __bfloat162float(h1.y));
    *(__nv_bfloat162*)(g_s_h + flat)     = h0; *(__nv_bfloat162*)(g_s_h + flat + 2) = h1;
    *(__nv_bfloat162*)(g_s_l + flat)     = l0; *(__nv_bfloat162*)(g_s_l + flat + 2) = l1;
}

// ---------------- flash attention, split-bf16 mma ----------------
// Bq=128 (8 warps x m16), Bkv=64, d=64. Q fragments hoisted to registers;
// KV double-buffered via cp.async; softmax in exp2 domain (scale folded into Q).
#define ATP 72
#define STG (4*64*ATP)                      // bf16 elems per KV stage
#define AT_SMEM (2*STG*2)                   // 73728 bytes
__global__ __launch_bounds__(256, 2) void attn_mma_kernel()
{
    extern __shared__ __nv_bfloat16 smem_bf[];
    __nv_bfloat16* sKV = smem_bf;           // [stage][4 planes][64*ATP]

    const int tid = threadIdx.x, w = tid >> 5, lane = tid & 31;
    const int qt = blockIdx.x, bhid = blockIdx.y;
    const int b = bhid >> 3, h = bhid & 7;

    const size_t baseq = ((size_t)b*TT + (size_t)qt*128) * CC + h*DD;
    const size_t basek = ((size_t)b*TT) * CC + h*DD;
    const __nv_bfloat16* Qh_g = g_s_h + baseq;
    const __nv_bfloat16* Ql_g = g_s_l + baseq;
    const __nv_bfloat16* Kh_g = g_s_h + (size_t)MM*CC   + basek;
    const __nv_bfloat16* Kl_g = g_s_l + (size_t)MM*CC   + basek;
    const __nv_bfloat16* Vh_g = g_s_h + (size_t)2*MM*CC + basek;
    const __nv_bfloat16* Vl_g = g_s_l + (size_t)2*MM*CC + basek;

    auto issueKV = [&](int kt, int s){
        __nv_bfloat16* dst = sKV + (size_t)s * STG;
#pragma unroll
        for (int j = 0; j < 2; j++){
            int idx = tid*2 + j;                // 0..511
            int r = idx >> 3, cseg = (idx & 7) * 8;
            size_t g = (size_t)(kt*64 + r) * CC + cseg;
            int so = r*ATP + cseg;
            cpasync16(sm_u32(&dst[0*64*ATP + so]), Kh_g + g);
            cpasync16(sm_u32(&dst[1*64*ATP + so]), Kl_g + g);
            cpasync16(sm_u32(&dst[2*64*ATP + so]), Vh_g + g);
            cpasync16(sm_u32(&dst[3*64*ATP + so]), Vl_g + g);
        }
    };

    // start KV stage-0 fetch immediately (writes stage 0 only)
    issueKV(0, 0); cpcommit();

    // stage Q through the (currently idle) stage-1 buffer, extract frags, release
    __nv_bfloat16* Qh_s = sKV + STG;            // 128*ATP
    __nv_bfloat16* Ql_s = Qh_s + 128*ATP;       // 128*ATP  (exactly fills stage 1)
#pragma unroll
    for (int it = 0; it < 4; it++){
        int idx = tid + it * 256;               // 0..1023
        int r = idx >> 3, cseg = (idx & 7) * 8;
        *(uint4*)&Qh_s[r*ATP + cseg] = *(const uint4*)(Qh_g + (size_t)r*CC + cseg);
        *(uint4*)&Ql_s[r*ATP + cseg] = *(const uint4*)(Ql_g + (size_t)r*CC + cseg);
    }
    __syncthreads();
    uint32_t qh[4][4], ql[4][4];                // Q fragments live in registers for all kt
#pragma unroll
    for (int ks = 0; ks < 4; ks++){
        int aoff = (w*16 + (lane & 15)) * ATP + ks*16 + (lane >> 4) * 8;
        ldm4(qh[ks], sm_u32(&Qh_s[aoff]));
        ldm4(ql[ks], sm_u32(&Ql_s[aoff]));
    }
    __syncthreads();                            // stage 1 free for KV reuse

    float o[8][4] = {};
    float st_m[2] = {-INFINITY, -INFINITY};
    float st_l[2] = {0.f, 0.f};

    for (int kt = 0; kt < 32; kt++){
        int s = kt & 1;
        if (kt < 31){ issueKV(kt+1, s^1); cpcommit(); cpwait<1>(); }
        else cpwait<0>();
        __syncthreads();
        __nv_bfloat16* Kh = sKV + (size_t)s * STG;
        __nv_bfloat16* Kl = Kh + 64*ATP;
        __nv_bfloat16* Vh = Kl + 64*ATP;
        __nv_bfloat16* Vl = Vh + 64*ATP;

        // ---- S = Q K^T (already in log2e units) ----
        float sacc[8][4] = {};
#pragma unroll
        for (int ks = 0; ks < 4; ks++){         // d chunks of 16
#pragma unroll
            for (int nt2 = 0; nt2 < 4; nt2++){  // kv chunks of 16
                int koff = (nt2*16 + (lane & 7) + (lane >> 4)*8) * ATP
                         + ks*16 + ((lane >> 3) & 1)*8;
                uint32_t bh4[4], bl4[4];
                ldm4(bh4, sm_u32(&Kh[koff]));
                ldm4(bl4, sm_u32(&Kl[koff]));
                int nt = nt2*2;
                mma16816(sacc[nt],   qh[ks], bh4[0], bh4[1]);
                mma16816(sacc[nt],   qh[ks], bl4[0], bl4[1]);
                mma16816(sacc[nt],   ql[ks], bh4[0], bh4[1]);
                mma16816(sacc[nt+1], qh[ks], bh4[2], bh4[3]);
                mma16816(sacc[nt+1], qh[ks], bl4[2], bl4[3]);
                mma16816(sacc[nt+1], ql[ks], bh4[2], bh4[3]);
            }
        }

        // ---- online softmax in exp2 domain ----
        float lm0 = -INFINITY, lm1 = -INFINITY;
#pragma unroll
        for (int nt = 0; nt < 8; nt++){
            lm0 = fmaxf(lm0, fmaxf(sacc[nt][0], sacc[nt][1]));
            lm1 = fmaxf(lm1, fmaxf(sacc[nt][2], sacc[nt][3]));
        }
        lm0 = fmaxf(lm0, __shfl_xor_sync(0xffffffffu, lm0, 1));
        lm0 = fmaxf(lm0, __shfl_xor_sync(0xffffffffu, lm0, 2));
        lm1 = fmaxf(lm1, __shfl_xor_sync(0xffffffffu, lm1, 1));
        lm1 = fmaxf(lm1, __shfl_xor_sync(0xffffffffu, lm1, 2));
        float mn0 = fmaxf(st_m[0], lm0), mn1 = fmaxf(st_m[1], lm1);
        float f0 = exp2f(st_m[0] - mn0), f1 = exp2f(st_m[1] - mn1);
        st_m[0] = mn0; st_m[1] = mn1;
        float ls0 = 0.f, ls1 = 0.f;
#pragma unroll
        for (int nt = 0; nt < 8; nt++){
            sacc[nt][0] = exp2f(sacc[nt][0] - mn0);
            sacc[nt][1] = exp2f(sacc[nt][1] - mn0);
            sacc[nt][2] = exp2f(sacc[nt][2] - mn1);
            sacc[nt][3] = exp2f(sacc[nt][3] - mn1);
            ls0 += sacc[nt][0] + sacc[nt][1];
            ls1 += sacc[nt][2] + sacc[nt][3];
        }
        ls0 += __shfl_xor_sync(0xffffffffu, ls0, 1);
        ls0 += __shfl_xor_sync(0xffffffffu, ls0, 2);
        ls1 += __shfl_xor_sync(0xffffffffu, ls1, 1);
        ls1 += __shfl_xor_sync(0xffffffffu, ls1, 2);
        st_l[0] = st_l[0]*f0 + ls0; st_l[1] = st_l[1]*f1 + ls1;
#pragma unroll
        for (int nt = 0; nt < 8; nt++){
            o[nt][0] *= f0; o[nt][1] *= f0; o[nt][2] *= f1; o[nt][3] *= f1;
        }

        // ---- O += P V  (P from c-frags -> split a-frags, register-local) ----
#pragma unroll
        for (int ks = 0; ks < 4; ks++){         // kv chunks of 16
            uint32_t pah[4], pal[4];
            {
                float p0 = sacc[2*ks][0],   p1 = sacc[2*ks][1];
                float p2 = sacc[2*ks][2],   p3 = sacc[2*ks][3];
                float q0 = sacc[2*ks+1][0], q1 = sacc[2*ks+1][1];
                float q2 = sacc[2*ks+1][2], q3 = sacc[2*ks+1][3];
                __nv_bfloat16 hp0 = __float2bfloat16(p0), hp1 = __float2bfloat16(p1);
                __nv_bfloat16 hp2 = __float2bfloat16(p2), hp3 = __float2bfloat16(p3);
                __nv_bfloat16 hq0 = __float2bfloat16(q0), hq1 = __float2bfloat16(q1);
                __nv_bfloat16 hq2 = __float2bfloat16(q2), hq3 = __float2bfloat16(q3);
                pah[0] = packbf(p0, p1); pah[1] = packbf(p2, p3);
                pah[2] = packbf(q0, q1); pah[3] = packbf(q2, q3);
                pal[0] = packbf(p0 - __bfloat162float(hp0), p1 - __bfloat162float(hp1));
                pal[1] = packbf(p2 - __bfloat162float(hp2), p3 - __bfloat162float(hp3));
                pal[2] = packbf(q0 - __bfloat162float(hq0), q1 - __bfloat162float(hq1));
                pal[3] = packbf(q2 - __bfloat162float(hq2), q3 - __bfloat162float(hq3));
            }
#pragma unroll
            for (int nt2 = 0; nt2 < 4; nt2++){  // d chunks of 16
                int voff = (ks*16 + (lane & 7) + ((lane >> 3) & 1)*8) * ATP
                         + nt2*16 + (lane >> 4)*8;
                uint32_t vh4[4], vl4[4];
                ldm4t(vh4, sm_u32(&Vh[voff]));
                ldm4t(vl4, sm_u32(&Vl[voff]));
                int nt = nt2*2;
                mma16816(o[nt],   pah, vh4[0], vh4[1]);
                mma16816(o[nt],   pah, vl4[0], vl4[1]);
                mma16816(o[nt],   pal, vh4[0], vh4[1]);
                mma16816(o[nt+1], pah, vh4[2], vh4[3]);
                mma16816(o[nt+1], pah, vl4[2], vl4[3]);
                mma16816(o[nt+1], pal, vh4[2], vh4[3]);
            }
        }
        __syncthreads();   // all warps done reading stage s before it is refilled
    }

    // ---- epilogue: normalize, split, write bf16 planes ----
    float il0 = 1.0f / st_l[0], il1 = 1.0f / st_l[1];
    int q0 = qt*128 + w*16 + (lane >> 2);
    size_t ob0 = ((size_t)b*TT + q0) * CC + h*DD;
    size_t ob1 = ob0 + (size_t)8*CC;
#pragma unroll
    for (int nt = 0; nt < 8; nt++){
        int c0 = nt*8 + (lane & 3)*2;
        float x0 = o[nt][0]*il0, x1 = o[nt][1]*il0;
        float y0 = o[nt][2]*il1, y1 = o[nt][3]*il1;
        __nv_bfloat162 xh, xl, yh, yl;
        xh.x = __float2bfloat16(x0); xl.x = __float2bfloat16(x0 - __bfloat162float(xh.x));
        xh.y = __float2bfloat16(x1); xl.y = __float2bfloat16(x1 - __bfloat162float(xh.y));
        yh.x = __float2bfloat16(y0); yl.x = __float2bfloat16(y0 - __bfloat162float(yh.x));
        yh.y = __float2bfloat16(y1); yl.y = __float2bfloat16(y1 - __bfloat162float(yh.y));
        *(__nv_bfloat162*)(g_a_h + ob0 + c0) = xh;
        *(__nv_bfloat162*)(g_a_l + ob0 + c0) = xl;
        *(__nv_bfloat162*)(g_a_h + ob1 + c0) = yh;
        *(__nv_bfloat162*)(g_a_l + ob1 + c0) = yl;
    }
}

// ---------------- launch ----------------
extern "C" void kernel_launch(void* const* d_in, const int* in_sizes, int n_in,
                              void* d_out, int out_size)
{
    (void)in_sizes; (void)n_in; (void)out_size;
    const float* X  = (const float*)d_in[0];
    const float* Wq = (const float*)d_in[1];
    const float* Wk = (const float*)d_in[2];
    const float* Wv = (const float*)d_in[3];
    const float* Wo = (const float*)d_in[4];
    const float* bo = (const float*)d_in[5];
    float* out = (float*)d_out;

    cudaFuncSetAttribute(attn_mma_kernel,
                         cudaFuncAttributeMaxDynamicSharedMemorySize, AT_SMEM);

    split_x_kernel<<<(size_t)MM*CC/1024, 256>>>(X);
    split_w4_kernel<<<dim3(CC*CC/1024, 4), 256>>>(Wq, Wk, Wv, Wo);
    gemm_mma_kernel<<<dim3(MM/64, CC/64, 3), 256>>>(0, 0, nullptr, nullptr, nullptr);
    sumsq_partial_kernel<<<dim3(NCHUNK, BB, 3), 512>>>();
    inv_finalize_kernel<<<dim3(3*BB), 512>>>();
    scale_split_kernel<<<(3u*MM*CC/4)/256, 256>>>();
    attn_mma_kernel<<<dim3(TT/128, BB*HH), 256, AT_SMEM>>>();
    gemm_mma_kernel<<<dim3(MM/64, CC/64, 1), 256>>>(1, 1, bo, X, out);
}